// round 2
// baseline (speedup 1.0000x reference)
#include <cuda_runtime.h>
#include <cstdint>

#define C_TOT 256
#define H_TOT 56
#define W_TOT 56
#define HW    3136
#define M_TOT 100352   // 32*56*56
#define CI    1024

// ---------------- scratch (static device globals; no allocations) ----------
__device__ float g_y[(size_t)M_TOT * C_TOT];   // NHWC, BN'd, tf32-rounded
__device__ float g_h[(size_t)M_TOT * CI];      // GELU output, tf32-rounded
__device__ float g_w1[CI * C_TOT];             // fc1_w tf32-rounded
__device__ float g_w2[C_TOT * CI];             // fc2_w tf32-rounded

__device__ __forceinline__ float to_tf32(float x) {
    uint32_t u;
    asm("cvt.rna.tf32.f32 %0, %1;" : "=r"(u) : "f"(x));
    return __uint_as_float(u);
}

__device__ __forceinline__ float gelu_exact(float v) {
    return 0.5f * v * (1.0f + erff(v * 0.70710678118654752440f));
}

// ---------------- kernel 1: round weights to tf32 --------------------------
__global__ void convert_weights_kernel(const float* __restrict__ fc1,
                                       const float* __restrict__ fc2) {
    int i = blockIdx.x * blockDim.x + threadIdx.x;
    if (i < CI * C_TOT) {
        g_w1[i] = to_tf32(fc1[i]);
        g_w2[i] = to_tf32(fc2[i]);
    }
}

// ---------------- kernel 2: NeoCell + BN -> y (NHWC, tf32) ------------------
// CTA: one batch b, one 4-row strip (hs), one 32-channel chunk.
// smem tile [32ch][4h][56w], channel stride 229 (gcd(229%32=5,32)=1 -> conflict-free).
__global__ __launch_bounds__(256)
void neocell_bn_kernel(const float* __restrict__ x,
                       const float* __restrict__ wa1, const float* __restrict__ wb1,
                       const float* __restrict__ wa2, const float* __restrict__ wb2,
                       const float* __restrict__ bnw, const float* __restrict__ bnb,
                       const float* __restrict__ bnm, const float* __restrict__ bnv) {
    __shared__ float tile[32 * 229];
    const int hs = blockIdx.x;        // 0..13
    const int c0 = blockIdx.y * 32;   // 0..224
    const int b  = blockIdx.z;
    const int h0 = hs * 4;

    const float* xb = x + ((size_t)b * C_TOT + c0) * HW + (size_t)h0 * W_TOT;
    for (int idx = threadIdx.x; idx < 32 * 4 * 56; idx += 256) {
        int c = idx / 224, r = idx % 224;
        int hh = r / 56, w = r % 56;
        tile[c * 229 + hh * 57 + w] = xb[(size_t)c * HW + hh * W_TOT + w];
    }
    __syncthreads();

    const int t  = threadIdx.x;
    const int c  = t & 31;
    const int s  = t >> 5;            // 0..7
    const int gc = c0 + c;
    const float scale = bnw[gc] * rsqrtf(bnv[gc] + 1e-5f);
    const float shift = bnb[gc] - bnm[gc] * scale;
    float* ybase = g_y + ((size_t)b * H_TOT + h0) * W_TOT * C_TOT + gc;
    const float* tc = tile + c * 229;

    if (gc < 128) {
        // k = 2 group
        const float a00 = wa1[gc*4+0], a01 = wa1[gc*4+1], a10 = wa1[gc*4+2], a11 = wa1[gc*4+3];
        const float b00 = wb1[gc*4+0], b01 = wb1[gc*4+1], b10 = wb1[gc*4+2], b11 = wb1[gc*4+3];
        for (int bi = s; bi < 56; bi += 8) {
            int n = bi / 28, m = bi % 28;     // n: block-row in strip (2), m: block-col (28)
            const float* tp = tc + n * 2 * 57 + m * 2;
            float x00 = tp[0],  x01 = tp[1];
            float x10 = tp[57], x11 = tp[58];
            float t00 = a00 * x00 + a01 * x10;
            float t01 = a00 * x01 + a01 * x11;
            float t10 = a10 * x00 + a11 * x10;
            float t11 = a10 * x01 + a11 * x11;
            float y00 = t00 * b00 + t01 * b10;
            float y01 = t00 * b01 + t01 * b11;
            float y10 = t10 * b00 + t11 * b10;
            float y11 = t10 * b01 + t11 * b11;
            size_t base = ((size_t)(n * 2) * 56 + m * 2) * (size_t)C_TOT;
            ybase[base]                = to_tf32(y00 * scale + shift);
            ybase[base + 256]          = to_tf32(y01 * scale + shift);
            ybase[base + 56 * 256]     = to_tf32(y10 * scale + shift);
            ybase[base + 57 * 256]     = to_tf32(y11 * scale + shift);
        }
    } else {
        // k = 4 group: the 4-row strip is exactly one block row
        const float* wap = wa2 + (size_t)(gc - 128) * 16;
        const float* wbp = wb2 + (size_t)(gc - 128) * 16;
        float a[4][4], bw[4][4];
        #pragma unroll
        for (int i = 0; i < 4; i++)
            #pragma unroll
            for (int j = 0; j < 4; j++) { a[i][j] = wap[i*4+j]; bw[i][j] = wbp[i*4+j]; }
        for (int m = s; m < 14; m += 8) {
            float xv[4][4];
            #pragma unroll
            for (int i = 0; i < 4; i++)
                #pragma unroll
                for (int j = 0; j < 4; j++) xv[i][j] = tc[i * 57 + m * 4 + j];
            float tv[4][4];
            #pragma unroll
            for (int p = 0; p < 4; p++)
                #pragma unroll
                for (int j = 0; j < 4; j++)
                    tv[p][j] = a[p][0]*xv[0][j] + a[p][1]*xv[1][j]
                             + a[p][2]*xv[2][j] + a[p][3]*xv[3][j];
            #pragma unroll
            for (int p = 0; p < 4; p++)
                #pragma unroll
                for (int q = 0; q < 4; q++) {
                    float v = tv[p][0]*bw[0][q] + tv[p][1]*bw[1][q]
                            + tv[p][2]*bw[2][q] + tv[p][3]*bw[3][q];
                    ybase[((size_t)(p * 56) + m * 4 + q) * (size_t)C_TOT] =
                        to_tf32(v * scale + shift);
                }
        }
    }
}

// ---------------- GEMM (TN: C[m,n] = sum_k A[m,k]*B[n,k]), tf32 mma --------
// CTA tile 128x128, BK=16, 8 warps (4m x 2n), warp tile 32x64.
// MODE 1: A=g_y, B=g_w1, C=g_h with exact GELU + tf32 rounding.
// MODE 2: A=g_h, B=g_w2, C=outp (NCHW) + residual x.
#define BKQ        16
#define LDSTRIDE   20                   // 16 + 4 pad -> conflict-free LDSM
#define STAGE_F    (128 * LDSTRIDE)     // floats per matrix per stage

template<int K, int MODE>
__global__ __launch_bounds__(256)
void gemm_tn_kernel(float* __restrict__ outp, const float* __restrict__ xres) {
    __shared__ __align__(16) float sm[4 * STAGE_F];  // A(2 stages) then B(2 stages)
    const float* Amat = (MODE == 1) ? g_y : g_h;
    const float* Bmat = (MODE == 1) ? g_w1 : g_w2;
    constexpr int KT = K / BKQ;

    const int tid  = threadIdx.x;
    const int lane = tid & 31;
    const int warp = tid >> 5;
    const int wm   = warp & 3;
    const int wn   = warp >> 2;
    const int bm   = blockIdx.y * 128;
    const int bn   = blockIdx.x * 128;

    // global -> smem staging: 4 threads per row (16 floats), 64 rows, x2 row blocks
    const int lrow = tid >> 2;
    const int lk   = (tid & 3) * 4;
    const float* Ap = Amat + (size_t)(bm + lrow) * K + lk;
    const float* Bp = Bmat + (size_t)(bn + lrow) * K + lk;

    const uint32_t smb = (uint32_t)__cvta_generic_to_shared(sm);
    const uint32_t sa  = smb + (uint32_t)(lrow * LDSTRIDE + lk) * 4u;
    const uint32_t sb  = sa + (uint32_t)(2 * STAGE_F) * 4u;

    float acc[2][8][4];
    #pragma unroll
    for (int i = 0; i < 2; i++)
        #pragma unroll
        for (int j = 0; j < 8; j++)
            #pragma unroll
            for (int q = 0; q < 4; q++) acc[i][j][q] = 0.f;

    // ldmatrix source addressing (fragment layouts per PTX m16n8k8 tf32)
    const int arow = lane & 15;
    const int ak   = (lane >> 4) * 4;
    const int brow = (lane & 7) + ((lane >> 4) << 3);
    const int bk   = ((lane >> 3) & 1) * 4;
    const uint32_t abase = smb + (uint32_t)((wm * 32 + arow) * LDSTRIDE + ak) * 4u;
    const uint32_t bbase = smb + (uint32_t)(2 * STAGE_F + (wn * 64 + brow) * LDSTRIDE + bk) * 4u;

#define PREFETCH(ktv, stv) do {                                                          \
    const float* ap_ = Ap + (ktv) * BKQ;                                                 \
    const float* bp_ = Bp + (ktv) * BKQ;                                                 \
    uint32_t so_ = (uint32_t)((stv) * STAGE_F * 4);                                      \
    asm volatile("cp.async.cg.shared.global [%0], [%1], 16;\n"                           \
                 :: "r"(sa + so_), "l"(ap_));                                            \
    asm volatile("cp.async.cg.shared.global [%0], [%1], 16;\n"                           \
                 :: "r"(sa + so_ + 64u * LDSTRIDE * 4u), "l"(ap_ + (size_t)64 * K));     \
    asm volatile("cp.async.cg.shared.global [%0], [%1], 16;\n"                           \
                 :: "r"(sb + so_), "l"(bp_));                                            \
    asm volatile("cp.async.cg.shared.global [%0], [%1], 16;\n"                           \
                 :: "r"(sb + so_ + 64u * LDSTRIDE * 4u), "l"(bp_ + (size_t)64 * K));     \
    asm volatile("cp.async.commit_group;\n");                                            \
} while (0)

    PREFETCH(0, 0);
    for (int kt = 0; kt < KT; ++kt) {
        if (kt + 1 < KT) {
            PREFETCH(kt + 1, (kt + 1) & 1);
            asm volatile("cp.async.wait_group 1;\n");
        } else {
            asm volatile("cp.async.wait_group 0;\n");
        }
        __syncthreads();
        const uint32_t soff = (uint32_t)((kt & 1) * STAGE_F * 4);
        #pragma unroll
        for (int s = 0; s < 2; s++) {
            uint32_t af[2][4];
            #pragma unroll
            for (int mt = 0; mt < 2; mt++) {
                asm volatile("ldmatrix.sync.aligned.m8n8.x4.shared.b16 {%0,%1,%2,%3}, [%4];\n"
                    : "=r"(af[mt][0]), "=r"(af[mt][1]), "=r"(af[mt][2]), "=r"(af[mt][3])
                    : "r"(abase + soff + (uint32_t)((mt * 16 * LDSTRIDE + s * 8) * 4)));
            }
            #pragma unroll
            for (int j = 0; j < 4; j++) {
                uint32_t bf[4];
                asm volatile("ldmatrix.sync.aligned.m8n8.x4.shared.b16 {%0,%1,%2,%3}, [%4];\n"
                    : "=r"(bf[0]), "=r"(bf[1]), "=r"(bf[2]), "=r"(bf[3])
                    : "r"(bbase + soff + (uint32_t)((j * 16 * LDSTRIDE + s * 8) * 4)));
                #pragma unroll
                for (int mt = 0; mt < 2; mt++) {
                    asm volatile(
                        "mma.sync.aligned.m16n8k8.row.col.f32.tf32.tf32.f32 "
                        "{%0,%1,%2,%3}, {%4,%5,%6,%7}, {%8,%9}, {%0,%1,%2,%3};\n"
                        : "+f"(acc[mt][2*j][0]), "+f"(acc[mt][2*j][1]),
                          "+f"(acc[mt][2*j][2]), "+f"(acc[mt][2*j][3])
                        : "r"(af[mt][0]), "r"(af[mt][1]), "r"(af[mt][2]), "r"(af[mt][3]),
                          "r"(bf[0]), "r"(bf[1]));
                    asm volatile(
                        "mma.sync.aligned.m16n8k8.row.col.f32.tf32.tf32.f32 "
                        "{%0,%1,%2,%3}, {%4,%5,%6,%7}, {%8,%9}, {%0,%1,%2,%3};\n"
                        : "+f"(acc[mt][2*j+1][0]), "+f"(acc[mt][2*j+1][1]),
                          "+f"(acc[mt][2*j+1][2]), "+f"(acc[mt][2*j+1][3])
                        : "r"(af[mt][0]), "r"(af[mt][1]), "r"(af[mt][2]), "r"(af[mt][3]),
                          "r"(bf[2]), "r"(bf[3]));
                }
            }
        }
        __syncthreads();
    }
#undef PREFETCH

    if (MODE == 1) {
        // GELU, round to tf32, store h [M x 1024]
        #pragma unroll
        for (int mt = 0; mt < 2; mt++) {
            const int r0 = bm + wm * 32 + mt * 16 + (lane >> 2);
            #pragma unroll
            for (int j = 0; j < 8; j++) {
                const int nc = bn + wn * 64 + j * 8 + (lane & 3) * 2;
                float* p0 = g_h + (size_t)r0 * CI + nc;
                float* p1 = p0 + (size_t)8 * CI;
                float2 v0, v1;
                v0.x = to_tf32(gelu_exact(acc[mt][j][0]));
                v0.y = to_tf32(gelu_exact(acc[mt][j][1]));
                v1.x = to_tf32(gelu_exact(acc[mt][j][2]));
                v1.y = to_tf32(gelu_exact(acc[mt][j][3]));
                *(float2*)p0 = v0;
                *(float2*)p1 = v1;
            }
        }
    } else {
        // residual + NCHW store (per-column 8-row runs -> full 32B sectors)
        #pragma unroll
        for (int mt = 0; mt < 2; mt++) {
            const int r0 = bm + wm * 32 + mt * 16 + (lane >> 2);
            const int r1 = r0 + 8;
            const int b0 = r0 / HW, hw0 = r0 - b0 * HW;
            const int b1 = r1 / HW, hw1 = r1 - b1 * HW;
            const size_t base0 = (size_t)b0 * C_TOT * HW + hw0;
            const size_t base1 = (size_t)b1 * C_TOT * HW + hw1;
            #pragma unroll
            for (int j = 0; j < 8; j++) {
                const int nc = bn + wn * 64 + j * 8 + (lane & 3) * 2;
                size_t i0 = base0 + (size_t)nc * HW;
                outp[i0]      = acc[mt][j][0] + xres[i0];
                outp[i0 + HW] = acc[mt][j][1] + xres[i0 + HW];
                size_t i1 = base1 + (size_t)nc * HW;
                outp[i1]      = acc[mt][j][2] + xres[i1];
                outp[i1 + HW] = acc[mt][j][3] + xres[i1 + HW];
            }
        }
    }
}

// ---------------- launch ----------------------------------------------------
extern "C" void kernel_launch(void* const* d_in, const int* in_sizes, int n_in,
                              void* d_out, int out_size) {
    const float* x   = (const float*)d_in[0];
    const float* wa1 = (const float*)d_in[1];
    const float* wb1 = (const float*)d_in[2];
    const float* wa2 = (const float*)d_in[3];
    const float* wb2 = (const float*)d_in[4];
    const float* bnw = (const float*)d_in[5];
    const float* bnb = (const float*)d_in[6];
    const float* bnm = (const float*)d_in[7];
    const float* bnv = (const float*)d_in[8];
    const float* fc1 = (const float*)d_in[9];
    const float* fc2 = (const float*)d_in[10];
    float* out = (float*)d_out;

    convert_weights_kernel<<<(CI * C_TOT + 255) / 256, 256>>>(fc1, fc2);
    neocell_bn_kernel<<<dim3(14, 8, 32), 256>>>(x, wa1, wb1, wa2, wb2,
                                                bnw, bnb, bnm, bnv);
    gemm_tn_kernel<256, 1><<<dim3(8, 784), 256>>>(nullptr, nullptr);   // y @ fc1^T, GELU
    gemm_tn_kernel<1024, 2><<<dim3(2, 784), 256>>>(out, x);            // h @ fc2^T + x
}

// round 6
// speedup vs baseline: 1.0622x; 1.0622x over previous
#include <cuda_runtime.h>
#include <cstdint>

#define C_TOT 256
#define H_TOT 56
#define W_TOT 56
#define HW    3136
#define M_TOT 100352   // 32*56*56
#define CI    1024

// ---------------- scratch (static device globals; no allocations) ----------
__device__ float g_y[(size_t)M_TOT * C_TOT];   // NHWC, BN'd, tf32-rounded
__device__ float g_h[(size_t)M_TOT * CI];      // GELU output, tf32-rounded
__device__ float g_w1[CI * C_TOT];             // fc1_w tf32-rounded
__device__ float g_w2[C_TOT * CI];             // fc2_w tf32-rounded

__device__ __forceinline__ float to_tf32(float x) {
    uint32_t u;
    asm("cvt.rna.tf32.f32 %0, %1;" : "=r"(u) : "f"(x));
    return __uint_as_float(u);
}
__device__ __forceinline__ float gelu_exact(float v) {
    return 0.5f * v * (1.0f + erff(v * 0.70710678118654752440f));
}

// ---------------- kernel 1: round weights to tf32 --------------------------
__global__ void convert_weights_kernel(const float* __restrict__ fc1,
                                       const float* __restrict__ fc2) {
    int i = blockIdx.x * blockDim.x + threadIdx.x;
    if (i < CI * C_TOT) {
        g_w1[i] = to_tf32(fc1[i]);
        g_w2[i] = to_tf32(fc2[i]);
    }
}

// ---------------- kernel 2: NeoCell + BN -> y (NHWC, tf32) ------------------
__global__ __launch_bounds__(256)
void neocell_bn_kernel(const float* __restrict__ x,
                       const float* __restrict__ wa1, const float* __restrict__ wb1,
                       const float* __restrict__ wa2, const float* __restrict__ wb2,
                       const float* __restrict__ bnw, const float* __restrict__ bnb,
                       const float* __restrict__ bnm, const float* __restrict__ bnv) {
    __shared__ float tile[32 * 229];
    const int hs = blockIdx.x;
    const int c0 = blockIdx.y * 32;
    const int b  = blockIdx.z;
    const int h0 = hs * 4;

    const float* xb = x + ((size_t)b * C_TOT + c0) * HW + (size_t)h0 * W_TOT;
    for (int idx = threadIdx.x; idx < 32 * 4 * 56; idx += 256) {
        int c = idx / 224, r = idx % 224;
        int hh = r / 56, w = r % 56;
        tile[c * 229 + hh * 57 + w] = xb[(size_t)c * HW + hh * W_TOT + w];
    }
    __syncthreads();

    const int t  = threadIdx.x;
    const int c  = t & 31;
    const int s  = t >> 5;
    const int gc = c0 + c;
    const float scale = bnw[gc] * rsqrtf(bnv[gc] + 1e-5f);
    const float shift = bnb[gc] - bnm[gc] * scale;
    float* ybase = g_y + ((size_t)b * H_TOT + h0) * W_TOT * C_TOT + gc;
    const float* tc = tile + c * 229;

    if (gc < 128) {
        const float a00 = wa1[gc*4+0], a01 = wa1[gc*4+1], a10 = wa1[gc*4+2], a11 = wa1[gc*4+3];
        const float b00 = wb1[gc*4+0], b01 = wb1[gc*4+1], b10 = wb1[gc*4+2], b11 = wb1[gc*4+3];
        for (int bi = s; bi < 56; bi += 8) {
            int n = bi / 28, m = bi % 28;
            const float* tp = tc + n * 2 * 57 + m * 2;
            float x00 = tp[0],  x01 = tp[1];
            float x10 = tp[57], x11 = tp[58];
            float t00 = a00 * x00 + a01 * x10;
            float t01 = a00 * x01 + a01 * x11;
            float t10 = a10 * x00 + a11 * x10;
            float t11 = a10 * x01 + a11 * x11;
            float y00 = t00 * b00 + t01 * b10;
            float y01 = t00 * b01 + t01 * b11;
            float y10 = t10 * b00 + t11 * b10;
            float y11 = t10 * b01 + t11 * b11;
            size_t base = ((size_t)(n * 2) * 56 + m * 2) * (size_t)C_TOT;
            ybase[base]            = to_tf32(y00 * scale + shift);
            ybase[base + 256]      = to_tf32(y01 * scale + shift);
            ybase[base + 56 * 256] = to_tf32(y10 * scale + shift);
            ybase[base + 57 * 256] = to_tf32(y11 * scale + shift);
        }
    } else {
        const float* wap = wa2 + (size_t)(gc - 128) * 16;
        const float* wbp = wb2 + (size_t)(gc - 128) * 16;
        float a[4][4], bw[4][4];
        #pragma unroll
        for (int i = 0; i < 4; i++)
            #pragma unroll
            for (int j = 0; j < 4; j++) { a[i][j] = wap[i*4+j]; bw[i][j] = wbp[i*4+j]; }
        for (int m = s; m < 14; m += 8) {
            float xv[4][4];
            #pragma unroll
            for (int i = 0; i < 4; i++)
                #pragma unroll
                for (int j = 0; j < 4; j++) xv[i][j] = tc[i * 57 + m * 4 + j];
            float tv[4][4];
            #pragma unroll
            for (int p = 0; p < 4; p++)
                #pragma unroll
                for (int j = 0; j < 4; j++)
                    tv[p][j] = a[p][0]*xv[0][j] + a[p][1]*xv[1][j]
                             + a[p][2]*xv[2][j] + a[p][3]*xv[3][j];
            #pragma unroll
            for (int p = 0; p < 4; p++)
                #pragma unroll
                for (int q = 0; q < 4; q++) {
                    float v = tv[p][0]*bw[0][q] + tv[p][1]*bw[1][q]
                            + tv[p][2]*bw[2][q] + tv[p][3]*bw[3][q];
                    ybase[((size_t)(p * 56) + m * 4 + q) * (size_t)C_TOT] =
                        to_tf32(v * scale + shift);
                }
        }
    }
}

// ---------------- GEMM (TN: C[m,n] = sum_k A[m,k]*B[n,k]), tf32 mma --------
// CTA tile 128x128, BK=16, 8 warps (4m x 2n), warp tile 32x64.
// 4-stage cp.async ring, single __syncthreads per K-iteration, pipelined B frags.
#define BKQ        16
#define LDSTRIDE   20                   // 16 + 4 pad -> conflict-free LDSM
#define STAGE_F    (128 * LDSTRIDE)     // floats per matrix per stage
#define NSTAGE     4
#define GSMEM      (NSTAGE * 2 * STAGE_F * 4)   // 81920 bytes

template<int K, int MODE>
__global__ __launch_bounds__(256, 2)
void gemm_tn_kernel(float* __restrict__ outp, const float* __restrict__ xres) {
    extern __shared__ __align__(16) float sm[];
    const float* Amat = (MODE == 1) ? g_y : g_h;
    const float* Bmat = (MODE == 1) ? g_w1 : g_w2;
    constexpr int KT = K / BKQ;

    const int tid  = threadIdx.x;
    const int lane = tid & 31;
    const int warp = tid >> 5;
    const int wm   = warp & 3;
    const int wn   = warp >> 2;
    const int bm   = blockIdx.y * 128;
    const int bn   = blockIdx.x * 128;

    // global -> smem staging: 4 threads per row (16 floats), 64 rows, x2 row blocks
    const int lrow = tid >> 2;
    const int lk   = (tid & 3) * 4;
    const float* Ap = Amat + (size_t)(bm + lrow) * K + lk;
    const float* Bp = Bmat + (size_t)(bn + lrow) * K + lk;

    const uint32_t smb = (uint32_t)__cvta_generic_to_shared(sm);
    // per-stage layout: [A(128x20) | B(128x20)]
    const uint32_t sa  = smb + (uint32_t)(lrow * LDSTRIDE + lk) * 4u;
    const uint32_t sb  = sa + (uint32_t)STAGE_F * 4u;

    float acc[2][8][4];
    #pragma unroll
    for (int i = 0; i < 2; i++)
        #pragma unroll
        for (int j = 0; j < 8; j++)
            #pragma unroll
            for (int q = 0; q < 4; q++) acc[i][j][q] = 0.f;

    // ldmatrix source addressing (fragment layouts per PTX m16n8k8 tf32)
    const int arow = lane & 15;
    const int ak   = (lane >> 4) * 4;
    const int brow = (lane & 7) + ((lane >> 4) << 3);
    const int bk   = ((lane >> 3) & 1) * 4;
    const uint32_t abase = smb + (uint32_t)((wm * 32 + arow) * LDSTRIDE + ak) * 4u;
    const uint32_t bbase = smb + (uint32_t)(STAGE_F + (wn * 64 + brow) * LDSTRIDE + bk) * 4u;

#define PREFETCH(ktv, stv) do {                                                          \
    const float* ap_ = Ap + (ktv) * BKQ;                                                 \
    const float* bp_ = Bp + (ktv) * BKQ;                                                 \
    uint32_t so_ = (uint32_t)((stv) * 2 * STAGE_F * 4);                                  \
    asm volatile("cp.async.cg.shared.global [%0], [%1], 16;\n"                           \
                 :: "r"(sa + so_), "l"(ap_));                                            \
    asm volatile("cp.async.cg.shared.global [%0], [%1], 16;\n"                           \
                 :: "r"(sa + so_ + 64u * LDSTRIDE * 4u), "l"(ap_ + (size_t)64 * K));     \
    asm volatile("cp.async.cg.shared.global [%0], [%1], 16;\n"                           \
                 :: "r"(sb + so_), "l"(bp_));                                            \
    asm volatile("cp.async.cg.shared.global [%0], [%1], 16;\n"                           \
                 :: "r"(sb + so_ + 64u * LDSTRIDE * 4u), "l"(bp_ + (size_t)64 * K));     \
    asm volatile("cp.async.commit_group;\n");                                            \
} while (0)

#define LDSM(dst, addr)                                                                  \
    asm volatile("ldmatrix.sync.aligned.m8n8.x4.shared.b16 {%0,%1,%2,%3}, [%4];\n"       \
        : "=r"((dst)[0]), "=r"((dst)[1]), "=r"((dst)[2]), "=r"((dst)[3]) : "r"(addr))

#define MMA_PAIR(accj, afr, b0, b1)                                                      \
    asm volatile("mma.sync.aligned.m16n8k8.row.col.f32.tf32.tf32.f32 "                   \
        "{%0,%1,%2,%3}, {%4,%5,%6,%7}, {%8,%9}, {%0,%1,%2,%3};\n"                        \
        : "+f"((accj)[0]), "+f"((accj)[1]), "+f"((accj)[2]), "+f"((accj)[3])             \
        : "r"((afr)[0]), "r"((afr)[1]), "r"((afr)[2]), "r"((afr)[3]),                    \
          "r"(b0), "r"(b1))

    // prologue: fill stages 0..2
    PREFETCH(0, 0);
    PREFETCH(1, 1);
    PREFETCH(2, 2);

    for (int kt = 0; kt < KT; ++kt) {
        const int st = kt & (NSTAGE - 1);
        if (kt + 2 < KT)      asm volatile("cp.async.wait_group 2;\n");
        else if (kt + 1 < KT) asm volatile("cp.async.wait_group 1;\n");
        else                  asm volatile("cp.async.wait_group 0;\n");
        __syncthreads();
        if (kt + 3 < KT) PREFETCH(kt + 3, (kt + 3) & (NSTAGE - 1));

        const uint32_t soff = (uint32_t)(st * 2 * STAGE_F * 4);
        #pragma unroll
        for (int s = 0; s < 2; s++) {
            uint32_t af[2][4];
            LDSM(af[0], abase + soff + (uint32_t)((0 * 16 * LDSTRIDE + s * 8) * 4));
            LDSM(af[1], abase + soff + (uint32_t)((1 * 16 * LDSTRIDE + s * 8) * 4));
            uint32_t bf0[4], bf1[4];
            LDSM(bf0, bbase + soff + (uint32_t)((0 * 16 * LDSTRIDE + s * 8) * 4));
            // j = 0 (prefetch j=1)
            LDSM(bf1, bbase + soff + (uint32_t)((1 * 16 * LDSTRIDE + s * 8) * 4));
            MMA_PAIR(acc[0][0], af[0], bf0[0], bf0[1]);
            MMA_PAIR(acc[0][1], af[0], bf0[2], bf0[3]);
            MMA_PAIR(acc[1][0], af[1], bf0[0], bf0[1]);
            MMA_PAIR(acc[1][1], af[1], bf0[2], bf0[3]);
            // j = 1 (prefetch j=2)
            LDSM(bf0, bbase + soff + (uint32_t)((2 * 16 * LDSTRIDE + s * 8) * 4));
            MMA_PAIR(acc[0][2], af[0], bf1[0], bf1[1]);
            MMA_PAIR(acc[0][3], af[0], bf1[2], bf1[3]);
            MMA_PAIR(acc[1][2], af[1], bf1[0], bf1[1]);
            MMA_PAIR(acc[1][3], af[1], bf1[2], bf1[3]);
            // j = 2 (prefetch j=3)
            LDSM(bf1, bbase + soff + (uint32_t)((3 * 16 * LDSTRIDE + s * 8) * 4));
            MMA_PAIR(acc[0][4], af[0], bf0[0], bf0[1]);
            MMA_PAIR(acc[0][5], af[0], bf0[2], bf0[3]);
            MMA_PAIR(acc[1][4], af[1], bf0[0], bf0[1]);
            MMA_PAIR(acc[1][5], af[1], bf0[2], bf0[3]);
            // j = 3
            MMA_PAIR(acc[0][6], af[0], bf1[0], bf1[1]);
            MMA_PAIR(acc[0][7], af[0], bf1[2], bf1[3]);
            MMA_PAIR(acc[1][6], af[1], bf1[0], bf1[1]);
            MMA_PAIR(acc[1][7], af[1], bf1[2], bf1[3]);
        }
    }
#undef PREFETCH
#undef LDSM
#undef MMA_PAIR

    if (MODE == 1) {
        // GELU, round to tf32, store h [M x 1024]
        #pragma unroll
        for (int mt = 0; mt < 2; mt++) {
            const int r0 = bm + wm * 32 + mt * 16 + (lane >> 2);
            #pragma unroll
            for (int j = 0; j < 8; j++) {
                const int nc = bn + wn * 64 + j * 8 + (lane & 3) * 2;
                float* p0 = g_h + (size_t)r0 * CI + nc;
                float* p1 = p0 + (size_t)8 * CI;
                float2 v0, v1;
                v0.x = to_tf32(gelu_exact(acc[mt][j][0]));
                v0.y = to_tf32(gelu_exact(acc[mt][j][1]));
                v1.x = to_tf32(gelu_exact(acc[mt][j][2]));
                v1.y = to_tf32(gelu_exact(acc[mt][j][3]));
                *(float2*)p0 = v0;
                *(float2*)p1 = v1;
            }
        }
    } else {
        // residual + NCHW store (per-column 8-row runs -> full 32B sectors)
        #pragma unroll
        for (int mt = 0; mt < 2; mt++) {
            const int r0 = bm + wm * 32 + mt * 16 + (lane >> 2);
            const int r1 = r0 + 8;
            const int b0 = r0 / HW, hw0 = r0 - b0 * HW;
            const int b1 = r1 / HW, hw1 = r1 - b1 * HW;
            const size_t base0 = (size_t)b0 * C_TOT * HW + hw0;
            const size_t base1 = (size_t)b1 * C_TOT * HW + hw1;
            #pragma unroll
            for (int j = 0; j < 8; j++) {
                const int nc = bn + wn * 64 + j * 8 + (lane & 3) * 2;
                size_t i0 = base0 + (size_t)nc * HW;
                outp[i0]      = acc[mt][j][0] + xres[i0];
                outp[i0 + HW] = acc[mt][j][1] + xres[i0 + HW];
                size_t i1 = base1 + (size_t)nc * HW;
                outp[i1]      = acc[mt][j][2] + xres[i1];
                outp[i1 + HW] = acc[mt][j][3] + xres[i1 + HW];
            }
        }
    }
}

// ---------------- launch ----------------------------------------------------
extern "C" void kernel_launch(void* const* d_in, const int* in_sizes, int n_in,
                              void* d_out, int out_size) {
    const float* x   = (const float*)d_in[0];
    const float* wa1 = (const float*)d_in[1];
    const float* wb1 = (const float*)d_in[2];
    const float* wa2 = (const float*)d_in[3];
    const float* wb2 = (const float*)d_in[4];
    const float* bnw = (const float*)d_in[5];
    const float* bnb = (const float*)d_in[6];
    const float* bnm = (const float*)d_in[7];
    const float* bnv = (const float*)d_in[8];
    const float* fc1 = (const float*)d_in[9];
    const float* fc2 = (const float*)d_in[10];
    float* out = (float*)d_out;

    cudaFuncSetAttribute(gemm_tn_kernel<256, 1>,
                         cudaFuncAttributeMaxDynamicSharedMemorySize, GSMEM);
    cudaFuncSetAttribute(gemm_tn_kernel<1024, 2>,
                         cudaFuncAttributeMaxDynamicSharedMemorySize, GSMEM);

    convert_weights_kernel<<<(CI * C_TOT + 255) / 256, 256>>>(fc1, fc2);
    neocell_bn_kernel<<<dim3(14, 8, 32), 256>>>(x, wa1, wb1, wa2, wb2,
                                                bnw, bnb, bnm, bnv);
    gemm_tn_kernel<256, 1><<<dim3(8, 784), 256, GSMEM>>>(nullptr, nullptr);   // y @ fc1^T, GELU
    gemm_tn_kernel<1024, 2><<<dim3(2, 784), 256, GSMEM>>>(out, x);            // h @ fc2^T + x
}